// round 11
// baseline (speedup 1.0000x reference)
#include <cuda_runtime.h>

#define NN  50000
#define EE  1600000
#define FIN 128
#define HH  32
#define CC  16

typedef unsigned long long u64;

// ---- scratch (device globals; no allocation allowed) ----
__device__ int   g_degi[NN];       // edge count per dst (zeroed at end of each call)
__device__ float g_dinv[NN];
__device__ float g_xws[NN * HH];   // dinv-prescaled features (both layers)
__device__ float g_agg[NN * HH];   // aggregation accumulator

// ---- f32x2 helpers ----
__device__ __forceinline__ u64 fma2(u64 a, u64 b, u64 c) {
    u64 d; asm("fma.rn.f32x2 %0, %1, %2, %3;" : "=l"(d) : "l"(a), "l"(b), "l"(c)); return d;
}
__device__ __forceinline__ u64 mul2(u64 a, u64 b) {
    u64 d; asm("mul.rn.f32x2 %0, %1, %2;" : "=l"(d) : "l"(a), "l"(b)); return d;
}
__device__ __forceinline__ u64 pack2(float x, float y) {
    u64 d; asm("mov.b64 %0, {%1, %2};" : "=l"(d) : "f"(x), "f"(y)); return d;
}
__device__ __forceinline__ void unpack2(u64 v, float& lo, float& hi) {
    asm("mov.b64 {%0, %1}, %2;" : "=f"(lo), "=f"(hi) : "l"(v));
}

// ================================================================ degree count (int4-vectorized)
__global__ void k_count(const int* __restrict__ dst) {
    int t = blockIdx.x * blockDim.x + threadIdx.x;
    if (t < EE / 4) {
        int4 d = ((const int4*)dst)[t];
        atomicAdd(&g_degi[d.x], 1);
        atomicAdd(&g_degi[d.y], 1);
        atomicAdd(&g_degi[d.z], 1);
        atomicAdd(&g_degi[d.w], 1);
    }
}

// ================================================================ GEMM1: xws = agg = (x @ W1) * dinv[row]
// Register-tiled 128x32 per 256-thread block; thread = 8 rows x 2 cols as 8
// f32x2 accs packed over row-pairs. x staged transposed with XOR swizzle
// (conflict-free STS), consumed as broadcast LDS.128. Next tile prefetched to
// registers during compute. dinv computed here (rsqrt of count+1) and saved.
#define XST 132
__global__ void __launch_bounds__(256) k_gemm1(const float* __restrict__ x,
                                               const float* __restrict__ W1) {
    __shared__ u64   Ws2[FIN][HH];     // 32KB: Ws2[k][c] = (W[k][c], W[k][c])
    __shared__ float xsT[32][XST];     // 16.9KB, swizzled transpose tile

    int tid = threadIdx.x;
    int tx = tid & 15;                 // col-pair 0..15
    int ty = tid >> 4;                 // row-octet 0..15
    int r0 = ty * 8;
    int base = blockIdx.x * 128;

    for (int i = tid; i < FIN * HH; i += 256) {
        float f = W1[i];
        Ws2[i >> 5][i & 31] = pack2(f, f);
    }

    // prefetch tile 0
    float4 pf[4];
#pragma unroll
    for (int p = 0; p < 4; p++) {
        int idx = p * 256 + tid;
        int r = idx >> 3, j4 = idx & 7;
        int gr = base + r;
        pf[p] = make_float4(0.f, 0.f, 0.f, 0.f);
        if (gr < NN) pf[p] = *(const float4*)(x + gr * FIN + j4 * 4);
    }

    u64 acc[8];
#pragma unroll
    for (int q = 0; q < 8; q++) acc[q] = 0ull;

    for (int kt = 0; kt < 4; kt++) {
        __syncthreads();               // previous tile fully consumed
#pragma unroll
        for (int p = 0; p < 4; p++) {
            int idx = p * 256 + tid;
            int r = idx >> 3, j4 = idx & 7;
            int rq = r ^ (j4 << 2);    // XOR swizzle -> conflict-free banks
            xsT[4 * j4 + 0][rq] = pf[p].x;
            xsT[4 * j4 + 1][rq] = pf[p].y;
            xsT[4 * j4 + 2][rq] = pf[p].z;
            xsT[4 * j4 + 3][rq] = pf[p].w;
        }
        __syncthreads();
        if (kt < 3) {                  // prefetch next tile (overlaps compute)
#pragma unroll
            for (int p = 0; p < 4; p++) {
                int idx = p * 256 + tid;
                int r = idx >> 3, j4 = idx & 7;
                int gr = base + r;
                pf[p] = make_float4(0.f, 0.f, 0.f, 0.f);
                if (gr < NN) pf[p] = *(const float4*)(x + gr * FIN + (kt + 1) * 32 + j4 * 4);
            }
        }
#pragma unroll
        for (int k = 0; k < 32; k++) {
            int sw = (k >> 2) << 2;
            ulonglong2 wv = *(const ulonglong2*)&Ws2[kt * 32 + k][2 * tx];
            ulonglong2 xa = *(const ulonglong2*)&xsT[k][r0 ^ sw];        // rows r0..r0+3
            ulonglong2 xb = *(const ulonglong2*)&xsT[k][(r0 + 4) ^ sw];  // rows r0+4..r0+7
            acc[0] = fma2(xa.x, wv.x, acc[0]);
            acc[1] = fma2(xa.x, wv.y, acc[1]);
            acc[2] = fma2(xa.y, wv.x, acc[2]);
            acc[3] = fma2(xa.y, wv.y, acc[3]);
            acc[4] = fma2(xb.x, wv.x, acc[4]);
            acc[5] = fma2(xb.x, wv.y, acc[5]);
            acc[6] = fma2(xb.y, wv.x, acc[6]);
            acc[7] = fma2(xb.y, wv.y, acc[7]);
        }
    }

    // epilogue: dinv = rsqrt(cnt+1); scale; store xws + agg (self-loop seed)
#pragma unroll
    for (int p = 0; p < 4; p++) {
        int rA = base + r0 + 2 * p;
        int rB = rA + 1;
        if (rA >= NN) break;
        float dA = rsqrtf((float)(g_degi[rA] + 1));
        float dB = (rB < NN) ? rsqrtf((float)(g_degi[rB] + 1)) : 0.0f;
        if (tx == 0) {
            g_dinv[rA] = dA;
            if (rB < NN) g_dinv[rB] = dB;
        }
        u64 dd = pack2(dA, dB);
#pragma unroll
        for (int c = 0; c < 2; c++) {
            u64 v = mul2(acc[2 * p + c], dd);
            float lo, hi;
            unpack2(v, lo, hi);
            int col = 2 * tx + c;
            g_xws[rA * HH + col] = lo;
            g_agg[rA * HH + col] = lo;
            if (rB < NN) {
                g_xws[rB * HH + col] = hi;
                g_agg[rB * HH + col] = hi;
            }
        }
    }
}

// ================================================================ edge scatter: agg[dst] += xws[src]
__global__ void k_scatter(const int* __restrict__ src, const int* __restrict__ dst) {
    int idx = blockIdx.x * blockDim.x + threadIdx.x;
    if (idx >= EE * 8) return;
    int e  = idx >> 3;
    int c4 = (idx & 7) << 2;
    int s = __ldg(src + e);
    int d = __ldg(dst + e);
    float4 v = *(const float4*)(g_xws + s * HH + c4);
    float* p = g_agg + d * HH + c4;
    asm volatile("red.global.add.v4.f32 [%0], {%1,%2,%3,%4};"
                 :: "l"(p), "f"(v.x), "f"(v.y), "f"(v.z), "f"(v.w)
                 : "memory");
}

// ================================================================ GEMM2 (layer-1 epilogue fused):
// h = tanh(dinv*agg + b1); xws = agg = (h @ W2) * dinv[row]
__global__ void k_gemm2(const float* __restrict__ b1, const float* __restrict__ W2) {
    __shared__ float Ws[HH * HH];
    int tid = threadIdx.x;
    for (int i = tid; i < HH * HH; i += 256) Ws[i] = W2[i];
    __syncthreads();
    int warp = tid >> 5, lane = tid & 31;
    int row = blockIdx.x * 8 + warp;
    if (row >= NN) return;
    float di = g_dinv[row];
    float h = tanhf(di * g_agg[row * HH + lane] + b1[lane]);
    float acc = 0.0f;
#pragma unroll
    for (int j = 0; j < 32; j++) {
        float hj = __shfl_sync(0xffffffffu, h, j);
        acc += hj * Ws[j * HH + lane];
    }
    float v = acc * di;
    g_xws[row * HH + lane] = v;
    g_agg[row * HH + lane] = v;
}

// ================================================================ layer-2 epilogue + classifier
// h = tanh(dinv*agg + b2) -> out[N*CC ..]; out[0..] = h @ Wc + bc
// Also zeroes g_degi for the next call (deterministic; module-load zeroes call 1).
__global__ void k_fin2(const float* __restrict__ b2, const float* __restrict__ Wc,
                       const float* __restrict__ bc, float* __restrict__ out) {
    __shared__ float Wcs[HH * CC];
    int tid = threadIdx.x;
    for (int i = tid; i < HH * CC; i += 256) Wcs[i] = Wc[i];
    __syncthreads();
    int warp = tid >> 5, lane = tid & 31;
    int row = blockIdx.x * 8 + warp;
    if (row >= NN) return;
    float di = g_dinv[row];
    float h = tanhf(di * g_agg[row * HH + lane] + b2[lane]);
    out[NN * CC + row * HH + lane] = h;      // second output: h [N,32]
    if (lane == 0) g_degi[row] = 0;          // reset for next call
    int cl = lane & (CC - 1);
    float acc = bc[cl];
#pragma unroll
    for (int j = 0; j < 32; j++) {
        float hj = __shfl_sync(0xffffffffu, h, j);
        acc += hj * Wcs[j * CC + cl];
    }
    if (lane < CC) out[row * CC + lane] = acc;   // first output: out [N,16]
}

// ================================================================ launch
extern "C" void kernel_launch(void* const* d_in, const int* in_sizes, int n_in,
                              void* d_out, int out_size) {
    const float* x  = (const float*)d_in[0];
    const int*   ei = (const int*)  d_in[1];
    const float* W1 = (const float*)d_in[2];
    const float* b1 = (const float*)d_in[3];
    const float* W2 = (const float*)d_in[4];
    const float* b2 = (const float*)d_in[5];
    const float* Wc = (const float*)d_in[6];
    const float* bc = (const float*)d_in[7];
    const int* src = ei;          // edge_index[0]
    const int* dst = ei + EE;     // edge_index[1]
    float* out = (float*)d_out;

    k_count  <<<(EE / 4 + 255) / 256, 256>>>(dst);

    k_gemm1  <<<(NN + 127) / 128, 256>>>(x, W1);
    k_scatter<<<(EE * 8 + 255) / 256, 256>>>(src, dst);

    k_gemm2  <<<(NN + 7) / 8, 256>>>(b1, W2);
    k_scatter<<<(EE * 8 + 255) / 256, 256>>>(src, dst);

    k_fin2   <<<(NN + 7) / 8, 256>>>(b2, Wc, bc, out);
}

// round 13
// speedup vs baseline: 1.1783x; 1.1783x over previous
#include <cuda_runtime.h>

#define NN  50000
#define EE  1600000
#define FIN 128
#define HH  32
#define CC  16

typedef unsigned long long u64;

// ---- scratch (device globals; no allocation allowed) ----
__device__ int   g_degi[NN];       // edge count per dst (zeroed at end of each call)
__device__ float g_dinv[NN];
__device__ float g_xws[NN * HH];   // dinv-prescaled features (both layers)
__device__ float g_agg[NN * HH];   // aggregation accumulator

// ---- f32x2 helpers ----
__device__ __forceinline__ u64 fma2(u64 a, u64 b, u64 c) {
    u64 d; asm("fma.rn.f32x2 %0, %1, %2, %3;" : "=l"(d) : "l"(a), "l"(b), "l"(c)); return d;
}
__device__ __forceinline__ u64 mul2(u64 a, u64 b) {
    u64 d; asm("mul.rn.f32x2 %0, %1, %2;" : "=l"(d) : "l"(a), "l"(b)); return d;
}
__device__ __forceinline__ u64 pack2(float x, float y) {
    u64 d; asm("mov.b64 %0, {%1, %2};" : "=l"(d) : "f"(x), "f"(y)); return d;
}
__device__ __forceinline__ void unpack2(u64 v, float& lo, float& hi) {
    asm("mov.b64 {%0, %1}, %2;" : "=f"(lo), "=f"(hi) : "l"(v));
}

// branch-free tanh: 1 - 2/(exp2(2x*log2e)+1); saturates correctly, rel err ~1e-6
__device__ __forceinline__ float tanh_fast(float x) {
    float e;
    asm("ex2.approx.f32 %0, %1;" : "=f"(e) : "f"(x * 2.8853900817779268f));
    float r;
    asm("rcp.approx.f32 %0, %1;" : "=f"(r) : "f"(e + 1.0f));
    return fmaf(-2.0f, r, 1.0f);
}

// ================================================================ degree count (int4-vectorized)
__global__ void k_count(const int* __restrict__ dst) {
    int t = blockIdx.x * blockDim.x + threadIdx.x;
    if (t < EE / 4) {
        int4 d = ((const int4*)dst)[t];
        atomicAdd(&g_degi[d.x], 1);
        atomicAdd(&g_degi[d.y], 1);
        atomicAdd(&g_degi[d.z], 1);
        atomicAdd(&g_degi[d.w], 1);
    }
}

// ================================================================ GEMM1: xws = agg = (x @ W1) * dinv[row]
// Register-tiled 128x32 per 256-thread block; thread = 8 rows x 2 cols as 8
// f32x2 accs packed over row-pairs. x staged transposed with XOR swizzle,
// consumed as broadcast LDS.128. Next tile prefetched during compute.
#define XST 132
__global__ void __launch_bounds__(256) k_gemm1(const float* __restrict__ x,
                                               const float* __restrict__ W1) {
    __shared__ u64   Ws2[FIN][HH];     // 32KB: Ws2[k][c] = (W[k][c], W[k][c])
    __shared__ float xsT[32][XST];     // swizzled transpose tile

    int tid = threadIdx.x;
    int tx = tid & 15;                 // col-pair 0..15
    int ty = tid >> 4;                 // row-octet 0..15
    int r0 = ty * 8;
    int base = blockIdx.x * 128;

    for (int i = tid; i < FIN * HH; i += 256) {
        float f = W1[i];
        Ws2[i >> 5][i & 31] = pack2(f, f);
    }

    float4 pf[4];
#pragma unroll
    for (int p = 0; p < 4; p++) {
        int idx = p * 256 + tid;
        int r = idx >> 3, j4 = idx & 7;
        int gr = base + r;
        pf[p] = make_float4(0.f, 0.f, 0.f, 0.f);
        if (gr < NN) pf[p] = *(const float4*)(x + gr * FIN + j4 * 4);
    }

    u64 acc[8];
#pragma unroll
    for (int q = 0; q < 8; q++) acc[q] = 0ull;

    for (int kt = 0; kt < 4; kt++) {
        __syncthreads();
#pragma unroll
        for (int p = 0; p < 4; p++) {
            int idx = p * 256 + tid;
            int r = idx >> 3, j4 = idx & 7;
            int rq = r ^ (j4 << 2);
            xsT[4 * j4 + 0][rq] = pf[p].x;
            xsT[4 * j4 + 1][rq] = pf[p].y;
            xsT[4 * j4 + 2][rq] = pf[p].z;
            xsT[4 * j4 + 3][rq] = pf[p].w;
        }
        __syncthreads();
        if (kt < 3) {
#pragma unroll
            for (int p = 0; p < 4; p++) {
                int idx = p * 256 + tid;
                int r = idx >> 3, j4 = idx & 7;
                int gr = base + r;
                pf[p] = make_float4(0.f, 0.f, 0.f, 0.f);
                if (gr < NN) pf[p] = *(const float4*)(x + gr * FIN + (kt + 1) * 32 + j4 * 4);
            }
        }
#pragma unroll
        for (int k = 0; k < 32; k++) {
            int sw = (k >> 2) << 2;
            ulonglong2 wv = *(const ulonglong2*)&Ws2[kt * 32 + k][2 * tx];
            ulonglong2 xa = *(const ulonglong2*)&xsT[k][r0 ^ sw];
            ulonglong2 xb = *(const ulonglong2*)&xsT[k][(r0 + 4) ^ sw];
            acc[0] = fma2(xa.x, wv.x, acc[0]);
            acc[1] = fma2(xa.x, wv.y, acc[1]);
            acc[2] = fma2(xa.y, wv.x, acc[2]);
            acc[3] = fma2(xa.y, wv.y, acc[3]);
            acc[4] = fma2(xb.x, wv.x, acc[4]);
            acc[5] = fma2(xb.x, wv.y, acc[5]);
            acc[6] = fma2(xb.y, wv.x, acc[6]);
            acc[7] = fma2(xb.y, wv.y, acc[7]);
        }
    }

    // epilogue: dinv = rsqrt(cnt+1); scale; store xws + agg (self-loop seed)
#pragma unroll
    for (int p = 0; p < 4; p++) {
        int rA = base + r0 + 2 * p;
        int rB = rA + 1;
        if (rA >= NN) break;
        float dA = rsqrtf((float)(g_degi[rA] + 1));
        float dB = (rB < NN) ? rsqrtf((float)(g_degi[rB] + 1)) : 0.0f;
        if (tx == 0) {
            g_dinv[rA] = dA;
            if (rB < NN) g_dinv[rB] = dB;
        }
        u64 dd = pack2(dA, dB);
#pragma unroll
        for (int c = 0; c < 2; c++) {
            u64 v = mul2(acc[2 * p + c], dd);
            float lo, hi;
            unpack2(v, lo, hi);
            int col = 2 * tx + c;
            g_xws[rA * HH + col] = lo;
            g_agg[rA * HH + col] = lo;
            if (rB < NN) {
                g_xws[rB * HH + col] = hi;
                g_agg[rB * HH + col] = hi;
            }
        }
    }
}

// ================================================================ edge scatter: agg[dst] += xws[src]
__global__ void k_scatter(const int* __restrict__ src, const int* __restrict__ dst) {
    int idx = blockIdx.x * blockDim.x + threadIdx.x;
    if (idx >= EE * 8) return;
    int e  = idx >> 3;
    int c4 = (idx & 7) << 2;
    int s = __ldg(src + e);
    int d = __ldg(dst + e);
    float4 v = *(const float4*)(g_xws + s * HH + c4);
    float* p = g_agg + d * HH + c4;
    asm volatile("red.global.add.v4.f32 [%0], {%1,%2,%3,%4};"
                 :: "l"(p), "f"(v.x), "f"(v.y), "f"(v.z), "f"(v.w)
                 : "memory");
}

// ================================================================ GEMM2 (layer-1 epilogue fused, shuffle-free):
// h = tanh(dinv*agg + b1) staged transposed; xws = agg = (h @ W2) * dinv[row]
__global__ void __launch_bounds__(256) k_gemm2(const float* __restrict__ b1,
                                               const float* __restrict__ W2) {
    __shared__ u64   Ws2[HH][HH];      // 8KB: Ws2[k][c] = (W2[k][c], W2[k][c])
    __shared__ float hsT[32][XST];     // swizzled transposed h tile
    __shared__ float b1s[HH];

    int tid = threadIdx.x;
    int tx = tid & 15;
    int ty = tid >> 4;
    int r0 = ty * 8;
    int base = blockIdx.x * 128;

    for (int i = tid; i < HH * HH; i += 256) {
        float f = W2[i];
        Ws2[i >> 5][i & 31] = pack2(f, f);
    }
    if (tid < HH) b1s[tid] = b1[tid];
    __syncthreads();

    // Phase A: h = tanh(dinv*agg + b1), stored transposed with XOR swizzle
#pragma unroll
    for (int p = 0; p < 4; p++) {
        int idx = p * 256 + tid;
        int r = idx >> 3, j4 = idx & 7;
        int gr = base + r;
        float4 hb = make_float4(0.f, 0.f, 0.f, 0.f);
        if (gr < NN) {
            float di = g_dinv[gr];
            float4 a = *(const float4*)(g_agg + gr * HH + 4 * j4);
            hb.x = tanh_fast(fmaf(di, a.x, b1s[4 * j4 + 0]));
            hb.y = tanh_fast(fmaf(di, a.y, b1s[4 * j4 + 1]));
            hb.z = tanh_fast(fmaf(di, a.z, b1s[4 * j4 + 2]));
            hb.w = tanh_fast(fmaf(di, a.w, b1s[4 * j4 + 3]));
        }
        int rq = r ^ (j4 << 2);
        hsT[4 * j4 + 0][rq] = hb.x;
        hsT[4 * j4 + 1][rq] = hb.y;
        hsT[4 * j4 + 2][rq] = hb.z;
        hsT[4 * j4 + 3][rq] = hb.w;
    }
    __syncthreads();

    // Phase B: register-tiled h @ W2
    u64 acc[8];
#pragma unroll
    for (int q = 0; q < 8; q++) acc[q] = 0ull;
#pragma unroll
    for (int k = 0; k < 32; k++) {
        int sw = (k >> 2) << 2;
        ulonglong2 wv = *(const ulonglong2*)&Ws2[k][2 * tx];
        ulonglong2 xa = *(const ulonglong2*)&hsT[k][r0 ^ sw];
        ulonglong2 xb = *(const ulonglong2*)&hsT[k][(r0 + 4) ^ sw];
        acc[0] = fma2(xa.x, wv.x, acc[0]);
        acc[1] = fma2(xa.x, wv.y, acc[1]);
        acc[2] = fma2(xa.y, wv.x, acc[2]);
        acc[3] = fma2(xa.y, wv.y, acc[3]);
        acc[4] = fma2(xb.x, wv.x, acc[4]);
        acc[5] = fma2(xb.x, wv.y, acc[5]);
        acc[6] = fma2(xb.y, wv.x, acc[6]);
        acc[7] = fma2(xb.y, wv.y, acc[7]);
    }

    // epilogue: scale by dinv, store xws + agg (self-loop seed)
#pragma unroll
    for (int p = 0; p < 4; p++) {
        int rA = base + r0 + 2 * p;
        int rB = rA + 1;
        if (rA >= NN) break;
        float dA = g_dinv[rA];
        float dB = (rB < NN) ? g_dinv[rB] : 0.0f;
        u64 dd = pack2(dA, dB);
#pragma unroll
        for (int c = 0; c < 2; c++) {
            u64 v = mul2(acc[2 * p + c], dd);
            float lo, hi;
            unpack2(v, lo, hi);
            int col = 2 * tx + c;
            g_xws[rA * HH + col] = lo;
            g_agg[rA * HH + col] = lo;
            if (rB < NN) {
                g_xws[rB * HH + col] = hi;
                g_agg[rB * HH + col] = hi;
            }
        }
    }
}

// ================================================================ layer-2 epilogue + classifier (shuffle-free)
// h = tanh(dinv*agg + b2) -> out[N*CC..] (coalesced) + staged transposed;
// out[0..] = h @ Wc + bc via register-tiled 128x16 GEMM. Resets g_degi.
__global__ void __launch_bounds__(256) k_fin2(const float* __restrict__ b2,
                                              const float* __restrict__ Wc,
                                              const float* __restrict__ bc,
                                              float* __restrict__ out) {
    __shared__ u64   Wd[HH][CC];       // 4KB: Wd[k][c] = (Wc[k][c], Wc[k][c])
    __shared__ float hsT[32][XST];
    __shared__ float b2s[HH];
    __shared__ float bcs[CC];

    int tid = threadIdx.x;
    int tx = tid & 15;                 // classifier column 0..15
    int ty = tid >> 4;
    int r0 = ty * 8;
    int base = blockIdx.x * 128;

    for (int i = tid; i < HH * CC; i += 256) {
        float f = Wc[i];
        Wd[i >> 4][i & 15] = pack2(f, f);
    }
    if (tid < HH) b2s[tid] = b2[tid];
    if (tid < CC) bcs[tid] = bc[tid];
    __syncthreads();

    // Phase A: h = tanh(dinv*agg + b2) -> out (h region) + transposed smem
#pragma unroll
    for (int p = 0; p < 4; p++) {
        int idx = p * 256 + tid;
        int r = idx >> 3, j4 = idx & 7;
        int gr = base + r;
        float4 hb = make_float4(0.f, 0.f, 0.f, 0.f);
        if (gr < NN) {
            float di = g_dinv[gr];
            float4 a = *(const float4*)(g_agg + gr * HH + 4 * j4);
            hb.x = tanh_fast(fmaf(di, a.x, b2s[4 * j4 + 0]));
            hb.y = tanh_fast(fmaf(di, a.y, b2s[4 * j4 + 1]));
            hb.z = tanh_fast(fmaf(di, a.z, b2s[4 * j4 + 2]));
            hb.w = tanh_fast(fmaf(di, a.w, b2s[4 * j4 + 3]));
            *(float4*)(out + NN * CC + gr * HH + 4 * j4) = hb;   // second output
            if (j4 == 0) g_degi[gr] = 0;                          // reset for next call
        }
        int rq = r ^ (j4 << 2);
        hsT[4 * j4 + 0][rq] = hb.x;
        hsT[4 * j4 + 1][rq] = hb.y;
        hsT[4 * j4 + 2][rq] = hb.z;
        hsT[4 * j4 + 3][rq] = hb.w;
    }
    __syncthreads();

    // Phase B: classifier GEMM, thread = 8 rows x 1 col (4 row-pair accs)
    u64 acc[4];
#pragma unroll
    for (int q = 0; q < 4; q++) acc[q] = 0ull;
#pragma unroll
    for (int k = 0; k < 32; k++) {
        int sw = (k >> 2) << 2;
        u64 wv = Wd[k][tx];
        ulonglong2 xa = *(const ulonglong2*)&hsT[k][r0 ^ sw];
        ulonglong2 xb = *(const ulonglong2*)&hsT[k][(r0 + 4) ^ sw];
        acc[0] = fma2(xa.x, wv, acc[0]);
        acc[1] = fma2(xa.y, wv, acc[1]);
        acc[2] = fma2(xb.x, wv, acc[2]);
        acc[3] = fma2(xb.y, wv, acc[3]);
    }
    float bcv = bcs[tx];
#pragma unroll
    for (int p = 0; p < 4; p++) {
        int rA = base + r0 + 2 * p;
        int rB = rA + 1;
        if (rA >= NN) break;
        float lo, hi;
        unpack2(acc[p], lo, hi);
        out[rA * CC + tx] = lo + bcv;                 // first output: out [N,16]
        if (rB < NN) out[rB * CC + tx] = hi + bcv;
    }
}

// ================================================================ launch
extern "C" void kernel_launch(void* const* d_in, const int* in_sizes, int n_in,
                              void* d_out, int out_size) {
    const float* x  = (const float*)d_in[0];
    const int*   ei = (const int*)  d_in[1];
    const float* W1 = (const float*)d_in[2];
    const float* b1 = (const float*)d_in[3];
    const float* W2 = (const float*)d_in[4];
    const float* b2 = (const float*)d_in[5];
    const float* Wc = (const float*)d_in[6];
    const float* bc = (const float*)d_in[7];
    const int* src = ei;          // edge_index[0]
    const int* dst = ei + EE;     // edge_index[1]
    float* out = (float*)d_out;

    k_count  <<<(EE / 4 + 255) / 256, 256>>>(dst);

    k_gemm1  <<<(NN + 127) / 128, 256>>>(x, W1);
    k_scatter<<<(EE * 8 + 255) / 256, 256>>>(src, dst);

    k_gemm2  <<<(NN + 127) / 128, 256>>>(b1, W2);
    k_scatter<<<(EE * 8 + 255) / 256, 256>>>(src, dst);

    k_fin2   <<<(NN + 127) / 128, 256>>>(b2, Wc, bc, out);
}